// round 1
// baseline (speedup 1.0000x reference)
#include <cuda_runtime.h>
#include <cuda_bf16.h>

// Problem constants: x (16,800,256), mu (64,256), prec (64) -> out (16, 64*256)
#define BB 16
#define TT 800
#define DD 256
#define KK 64
#define NROWS (BB*TT)          // 12800

typedef unsigned long long ull;

// ---------------- scratch (device globals; no allocation allowed) ------------
__device__ float g_R[NROWS * KK];   // softmax weights (unnormalized over T), 3.2MB
__device__ float g_S[BB * KK];      // sum over T of r
__device__ float g_musq[KK];
__device__ float g_p2[KK];

// ---------------- f32x2 helpers ----------------------------------------------
__device__ __forceinline__ ull pack2(float lo, float hi) {
    ull r; asm("mov.b64 %0,{%1,%2};" : "=l"(r) : "f"(lo), "f"(hi)); return r;
}
__device__ __forceinline__ ull fma2(ull a, ull b, ull c) {
    ull d; asm("fma.rn.f32x2 %0,%1,%2,%3;" : "=l"(d) : "l"(a), "l"(b), "l"(c)); return d;
}
__device__ __forceinline__ float2 unpack2(ull v) {
    float2 f; asm("mov.b64 {%0,%1},%2;" : "=f"(f.x), "=f"(f.y) : "l"(v)); return f;
}

union F4 { float4 f; ull u[2]; };

// ---------------- kernel 0: prep (musq, p2, zero S + out) --------------------
__global__ void prep_kernel(const float* __restrict__ mu,
                            const float* __restrict__ prec,
                            float* __restrict__ out) {
    if (blockIdx.x < 256) {
        // zero d_out: 262144 floats = 65536 float4 = 256 blocks * 256 threads
        ((float4*)out)[blockIdx.x * 256 + threadIdx.x] = make_float4(0.f, 0.f, 0.f, 0.f);
    } else {
        int tid = threadIdx.x;
        ((float4*)g_S)[tid] = make_float4(0.f, 0.f, 0.f, 0.f);  // 256*4 = 1024
        if (tid < KK) {
            const float4* m = (const float4*)mu + tid * (DD / 4);
            float s = 0.f;
            #pragma unroll 8
            for (int j = 0; j < DD / 4; j++) {
                float4 v = m[j];
                s += v.x * v.x + v.y * v.y + v.z * v.z + v.w * v.w;
            }
            g_musq[tid] = s;
            float p = prec[tid];
            g_p2[tid] = p * p;
        }
    }
}

// ---------------- kernel 1: llk GEMM + softmax --------------------------------
// Block: 64 rows x all 64 k. 256 threads; thread tile 4 rows x 4 k.
// D staged in 4 chunks of 64 floats. Pitch-66 smem (float2-granule) -> no conflicts.
#define PA 66
__global__ __launch_bounds__(256, 2)
void llk_kernel(const float* __restrict__ x, const float* __restrict__ mu) {
    __shared__ float sx[64 * PA];
    __shared__ float smu[64 * PA];
    __shared__ float sxsq[64];

    int tid  = threadIdx.x;
    int lane = tid & 31;
    int w    = tid >> 5;
    int kg   = tid >> 4;   // 0..15 -> k in [4kg, 4kg+4)
    int rg   = tid & 15;   // rows {rg, rg+16, rg+32, rg+48}
    int R0   = blockIdx.x * 64;

    if (tid < 64) sxsq[tid] = 0.f;

    ull acc[16];
    #pragma unroll
    for (int i = 0; i < 16; i++) acc[i] = 0ull;
    float myxsq[4] = {0.f, 0.f, 0.f, 0.f};

    const float4* x4  = (const float4*)x;
    const float4* mu4 = (const float4*)mu;

    for (int c = 0; c < 4; c++) {
        __syncthreads();
        // stage x chunk (64 rows x 64 floats) and mu chunk (64 k x 64 floats)
        #pragma unroll
        for (int ii = 0; ii < 4; ii++) {
            int idx = tid + 256 * ii;
            int r = idx >> 4, j = idx & 15;
            float4 v = x4[(R0 + r) * 64 + c * 16 + j];
            myxsq[ii] += v.x * v.x + v.y * v.y + v.z * v.z + v.w * v.w;
            float2* d = (float2*)(sx + r * PA + j * 4);
            d[0] = make_float2(v.x, v.y); d[1] = make_float2(v.z, v.w);
            float4 m = mu4[r * 64 + c * 16 + j];   // r doubles as k index (both 64)
            float2* dm = (float2*)(smu + r * PA + j * 4);
            dm[0] = make_float2(m.x, m.y); dm[1] = make_float2(m.z, m.w);
        }
        __syncthreads();
        // compute: 32 d-pairs per chunk, 16 FFMA2 each
        #pragma unroll 4
        for (int dp = 0; dp < 32; dp++) {
            ull xv[4], mv[4];
            #pragma unroll
            for (int i = 0; i < 4; i++)
                xv[i] = *(const ull*)(sx + (rg + 16 * i) * PA + 2 * dp);
            #pragma unroll
            for (int j = 0; j < 4; j++)
                mv[j] = *(const ull*)(smu + (kg * 4 + j) * PA + 2 * dp);
            #pragma unroll
            for (int i = 0; i < 4; i++)
                #pragma unroll
                for (int j = 0; j < 4; j++)
                    acc[i * 4 + j] = fma2(xv[i], mv[j], acc[i * 4 + j]);
        }
    }

    // commit xsq partials (staging rows were kg + 16*ii)
    #pragma unroll
    for (int ii = 0; ii < 4; ii++)
        atomicAdd(&sxsq[(tid >> 4) + 16 * ii], myxsq[ii]);
    __syncthreads();

    // dump G tile to smem (overlay on sx)
    float* sG = sx;
    #pragma unroll
    for (int i = 0; i < 4; i++) {
        int row = rg + 16 * i;
        #pragma unroll
        for (int j = 0; j < 4; j++) {
            float2 v = unpack2(acc[i * 4 + j]);
            sG[row * 64 + kg * 4 + j] = v.x + v.y;
        }
    }
    __syncthreads();

    // per-row softmax over K=64: warp w handles rows [8w, 8w+8)
    float mq0 = g_musq[lane], mq1 = g_musq[lane + 32];
    float pp0 = g_p2[lane],   pp1 = g_p2[lane + 32];
    for (int rr = 0; rr < 8; rr++) {
        int row  = w * 8 + rr;
        int grow = R0 + row;
        int b    = grow / TT;
        float xq = sxsq[row];
        float G0 = sG[row * 64 + lane];
        float G1 = sG[row * 64 + lane + 32];
        float l0 = -pp0 * (xq - 2.f * G0 + mq0);
        float l1 = -pp1 * (xq - 2.f * G1 + mq1);
        float m = fmaxf(l0, l1);
        #pragma unroll
        for (int o = 16; o; o >>= 1) m = fmaxf(m, __shfl_xor_sync(0xffffffffu, m, o));
        float e0 = __expf(l0 - m), e1 = __expf(l1 - m);
        float s = e0 + e1;
        #pragma unroll
        for (int o = 16; o; o >>= 1) s += __shfl_xor_sync(0xffffffffu, s, o);
        float inv = 1.f / s;
        float r0 = e0 * inv, r1 = e1 * inv;
        g_R[grow * 64 + lane]      = r0;
        g_R[grow * 64 + lane + 32] = r1;
        atomicAdd(&g_S[b * 64 + lane],      r0);
        atomicAdd(&g_S[b * 64 + lane + 32], r1);
    }
}

// ---------------- kernel 2: pooling GEMM P[b,k,d] = sum_t r*x -----------------
// grid 160 = 16 b x 10 chunks of 80 t. Block 256 threads; thread tile 8k x 8d.
__global__ __launch_bounds__(256, 2)
void pool_kernel(const float* __restrict__ x, float* __restrict__ out) {
    __shared__ float4 sx4[8 * 64];   // 8 rows x 256 floats
    __shared__ ull    srd[8 * 64];   // 8 rows x 64 k, duplicated f32x2

    int b  = blockIdx.x / 10;
    int ch = blockIdx.x % 10;
    int t0 = ch * 80;
    int tid = threadIdx.x;
    int kq = tid >> 5;   // warp id -> k0 = 8*kq (broadcast within warp)
    int dq = tid & 31;   // d0 = 8*dq

    ull acc[32];
    #pragma unroll
    for (int i = 0; i < 32; i++) acc[i] = 0ull;

    for (int st = 0; st < 10; st++) {
        int trow = b * TT + t0 + st * 8;
        __syncthreads();
        const float4* xg = (const float4*)x + trow * 64;
        sx4[tid]       = xg[tid];
        sx4[tid + 256] = xg[tid + 256];
        float2 rv = ((const float2*)(g_R + trow * 64))[tid];
        srd[2 * tid]     = pack2(rv.x, rv.x);
        srd[2 * tid + 1] = pack2(rv.y, rv.y);
        __syncthreads();
        #pragma unroll
        for (int tt = 0; tt < 8; tt++) {
            const ull* rk = &srd[tt * 64 + kq * 8];
            F4 xa, xb;
            xa.f = sx4[tt * 64 + dq * 2];
            xb.f = sx4[tt * 64 + dq * 2 + 1];
            #pragma unroll
            for (int kk = 0; kk < 8; kk++) {
                ull r2 = rk[kk];
                acc[kk * 4 + 0] = fma2(r2, xa.u[0], acc[kk * 4 + 0]);
                acc[kk * 4 + 1] = fma2(r2, xa.u[1], acc[kk * 4 + 1]);
                acc[kk * 4 + 2] = fma2(r2, xb.u[0], acc[kk * 4 + 2]);
                acc[kk * 4 + 3] = fma2(r2, xb.u[1], acc[kk * 4 + 3]);
            }
        }
    }

    float* ob = out + b * (KK * DD);
    int k0 = kq * 8, d0 = dq * 8;
    #pragma unroll
    for (int kk = 0; kk < 8; kk++)
        #pragma unroll
        for (int p = 0; p < 4; p++) {
            float2 v = unpack2(acc[kk * 4 + p]);
            atomicAdd(ob + (k0 + kk) * DD + d0 + p * 2,     v.x);
            atomicAdd(ob + (k0 + kk) * DD + d0 + p * 2 + 1, v.y);
        }
}

// ---------------- kernel 3: finalize out = (P - mu*S)/(S+1e-9) ---------------
__global__ void finalize_kernel(const float* __restrict__ mu, float* __restrict__ out) {
    int i = blockIdx.x * 256 + threadIdx.x;       // float4 index, 65536 total
    int flat = i * 4;
    int b = flat >> 14;
    int k = (flat >> 8) & 63;
    float s = g_S[b * 64 + k];
    float inv = 1.f / (s + 1e-9f);
    float4 p = ((const float4*)out)[i];
    float4 m = ((const float4*)mu)[i & 4095];
    float4 o;
    o.x = (p.x - m.x * s) * inv;
    o.y = (p.y - m.y * s) * inv;
    o.z = (p.z - m.z * s) * inv;
    o.w = (p.w - m.w * s) * inv;
    ((float4*)out)[i] = o;
}

// ---------------- launcher ----------------------------------------------------
extern "C" void kernel_launch(void* const* d_in, const int* in_sizes, int n_in,
                              void* d_out, int out_size) {
    const float* x    = (const float*)d_in[0];
    const float* mu   = (const float*)d_in[1];
    const float* prec = (const float*)d_in[2];
    float* out = (float*)d_out;

    prep_kernel<<<257, 256>>>(mu, prec, out);
    llk_kernel<<<200, 256>>>(x, mu);
    pool_kernel<<<160, 256>>>(x, out);
    finalize_kernel<<<256, 256>>>(mu, out);
}

// round 2
// speedup vs baseline: 1.5211x; 1.5211x over previous
#include <cuda_runtime.h>

// Problem constants: x (16,800,256), mu (64,256), prec (64) -> out (16, 64*256)
#define BB 16
#define TT 800
#define DD 256
#define KK 64

typedef unsigned long long ull;

// ---------------- scratch (device globals) ------------------------------------
__device__ float g_S[BB * KK];
__device__ float g_musq[KK];
__device__ float g_p2[KK];

// ---------------- f32x2 helpers ------------------------------------------------
__device__ __forceinline__ ull pack2(float lo, float hi) {
    ull r; asm("mov.b64 %0,{%1,%2};" : "=l"(r) : "f"(lo), "f"(hi)); return r;
}
__device__ __forceinline__ ull fma2(ull a, ull b, ull c) {
    ull d; asm("fma.rn.f32x2 %0,%1,%2,%3;" : "=l"(d) : "l"(a), "l"(b), "l"(c)); return d;
}
__device__ __forceinline__ float2 unpack2(ull v) {
    float2 f; asm("mov.b64 {%0,%1},%2;" : "=f"(f.x), "=f"(f.y) : "l"(v)); return f;
}

union F4 { float4 f; ull u[2]; };

// ---------------- kernel 0: prep (musq, p2, zero S + out) ----------------------
__global__ void prep_kernel(const float* __restrict__ mu,
                            const float* __restrict__ prec,
                            float* __restrict__ out) {
    if (blockIdx.x < 256) {
        ((float4*)out)[blockIdx.x * 256 + threadIdx.x] = make_float4(0.f, 0.f, 0.f, 0.f);
    } else {
        int tid = threadIdx.x;
        ((float4*)g_S)[tid] = make_float4(0.f, 0.f, 0.f, 0.f);
        if (tid < KK) {
            const float4* m = (const float4*)mu + tid * (DD / 4);
            float s = 0.f;
            #pragma unroll 8
            for (int j = 0; j < DD / 4; j++) {
                float4 v = m[j];
                s += v.x * v.x + v.y * v.y + v.z * v.z + v.w * v.w;
            }
            g_musq[tid] = s;
            float p = prec[tid];
            g_p2[tid] = p * p;
        }
    }
}

// ---------------- fused body: llk GEMM + softmax + pool GEMM -------------------
// NR rows of one batch b per block. 256 threads.
// Phase A: G[NR x 64] = X[NR x 256] * MU^T, smem-tiled, thread tile (NR/16) x 4.
// Phase B: per-row softmax over K=64 -> r kept in smem (dup-packed f32x2), S -> g_S.
// Phase C: P[64 x 256] += r^T * X, thread tile 8k x 8d, red-atomic into out.
template<int NR>
__device__ __forceinline__ void fused_body(int b, int trow0,
                                           const float* __restrict__ x,
                                           const float* __restrict__ mu,
                                           float* __restrict__ out) {
    constexpr int RT  = NR / 16;   // rows per thread in phase A
    constexpr int RPW = NR / 8;    // rows per warp in phase B

    extern __shared__ char sm[];
    float* sx   = (float*)sm;                                   // NR*66 floats
    float* smu  = (float*)(sm + NR * 66 * 4);                   // 64*66 floats
    ull*   srd  = (ull*)  (sm + (NR * 66 + 64 * 66) * 4);       // NR*64 ull
    float* sxsq = (float*)(sm + (NR * 66 + 64 * 66) * 4 + NR * 64 * 8);  // NR floats
    float4* xs  = (float4*)sm;   // phase C overlay: 16*64 float4 = 16KB
    float*  sG  = sx;            // phase B overlay: NR*64 floats

    int tid  = threadIdx.x;
    int lane = tid & 31;
    int w    = tid >> 5;
    int kg   = tid >> 4;   // k group: k in [4kg, 4kg+4)
    int rg   = tid & 15;   // rows {rg, rg+16, ...}

    if (tid < NR) sxsq[tid] = 0.f;

    ull acc[RT * 4];
    #pragma unroll
    for (int i = 0; i < RT * 4; i++) acc[i] = 0ull;
    float myxsq[RT];
    #pragma unroll
    for (int i = 0; i < RT; i++) myxsq[i] = 0.f;

    const float4* x4  = (const float4*)x;
    const float4* mu4 = (const float4*)mu;

    // ---- Phase A: distance GEMM ----
    for (int c = 0; c < 4; c++) {
        __syncthreads();
        #pragma unroll
        for (int ii = 0; ii < RT; ii++) {
            int idx = tid + 256 * ii;
            int r = idx >> 4, j = idx & 15;
            float4 v = x4[(trow0 + r) * 64 + c * 16 + j];
            myxsq[ii] += v.x * v.x + v.y * v.y + v.z * v.z + v.w * v.w;
            float2* d = (float2*)(sx + r * 66 + j * 4);
            d[0] = make_float2(v.x, v.y); d[1] = make_float2(v.z, v.w);
        }
        #pragma unroll
        for (int ii = 0; ii < 4; ii++) {
            int idx = tid + 256 * ii;
            int r = idx >> 4, j = idx & 15;
            float4 m = mu4[r * 64 + c * 16 + j];
            float2* dm = (float2*)(smu + r * 66 + j * 4);
            dm[0] = make_float2(m.x, m.y); dm[1] = make_float2(m.z, m.w);
        }
        __syncthreads();
        #pragma unroll 4
        for (int dp = 0; dp < 32; dp++) {
            ull xv[RT], mv[4];
            #pragma unroll
            for (int i = 0; i < RT; i++)
                xv[i] = *(const ull*)(sx + (rg + 16 * i) * 66 + 2 * dp);
            #pragma unroll
            for (int j = 0; j < 4; j++)
                mv[j] = *(const ull*)(smu + (kg * 4 + j) * 66 + 2 * dp);
            #pragma unroll
            for (int i = 0; i < RT; i++)
                #pragma unroll
                for (int j = 0; j < 4; j++)
                    acc[i * 4 + j] = fma2(xv[i], mv[j], acc[i * 4 + j]);
        }
    }

    // commit xsq partials (thread staged rows (tid>>4)+16*ii)
    #pragma unroll
    for (int ii = 0; ii < RT; ii++)
        atomicAdd(&sxsq[(tid >> 4) + 16 * ii], myxsq[ii]);
    __syncthreads();

    // dump G tile to smem (overlay on sx)
    #pragma unroll
    for (int i = 0; i < RT; i++) {
        int row = rg + 16 * i;
        #pragma unroll
        for (int j = 0; j < 4; j++) {
            float2 v = unpack2(acc[i * 4 + j]);
            sG[row * 64 + kg * 4 + j] = v.x + v.y;
        }
    }
    __syncthreads();

    // ---- Phase B: softmax over K, r -> srd (dup-packed), S -> g_S ----
    {
        float mq0 = g_musq[lane], mq1 = g_musq[lane + 32];
        float pp0 = g_p2[lane],   pp1 = g_p2[lane + 32];
        float ss0 = 0.f, ss1 = 0.f;
        #pragma unroll
        for (int rr = 0; rr < RPW; rr++) {
            int row = w * RPW + rr;
            float xq = sxsq[row];
            float G0 = sG[row * 64 + lane];
            float G1 = sG[row * 64 + lane + 32];
            float l0 = -pp0 * (xq - 2.f * G0 + mq0);
            float l1 = -pp1 * (xq - 2.f * G1 + mq1);
            float m = fmaxf(l0, l1);
            #pragma unroll
            for (int o = 16; o; o >>= 1) m = fmaxf(m, __shfl_xor_sync(0xffffffffu, m, o));
            float e0 = __expf(l0 - m), e1 = __expf(l1 - m);
            float s = e0 + e1;
            #pragma unroll
            for (int o = 16; o; o >>= 1) s += __shfl_xor_sync(0xffffffffu, s, o);
            float inv = 1.f / s;
            float r0 = e0 * inv, r1 = e1 * inv;
            srd[row * 64 + lane]      = pack2(r0, r0);
            srd[row * 64 + lane + 32] = pack2(r1, r1);
            ss0 += r0; ss1 += r1;
        }
        atomicAdd(&g_S[b * 64 + lane],      ss0);
        atomicAdd(&g_S[b * 64 + lane + 32], ss1);
    }

    // ---- Phase C: pool GEMM, thread tile 8k x 8d ----
    // k0 = 8*w (warp-uniform -> broadcast r loads), d = {4*lane..} and {128+4*lane..}
    ull acc2[32];
    #pragma unroll
    for (int i = 0; i < 32; i++) acc2[i] = 0ull;

    for (int st = 0; st < NR / 16; st++) {
        __syncthreads();
        #pragma unroll
        for (int ii = 0; ii < 4; ii++) {
            int idx = tid + 256 * ii;
            xs[idx] = x4[(trow0 + st * 16 + (idx >> 6)) * 64 + (idx & 63)];
        }
        __syncthreads();
        #pragma unroll
        for (int tt = 0; tt < 16; tt++) {
            const ull* rk = &srd[(st * 16 + tt) * 64 + w * 8];
            F4 xa, xb;
            xa.f = xs[tt * 64 + lane];
            xb.f = xs[tt * 64 + 32 + lane];
            #pragma unroll
            for (int kk = 0; kk < 8; kk++) {
                ull r2 = rk[kk];
                acc2[kk * 4 + 0] = fma2(r2, xa.u[0], acc2[kk * 4 + 0]);
                acc2[kk * 4 + 1] = fma2(r2, xa.u[1], acc2[kk * 4 + 1]);
                acc2[kk * 4 + 2] = fma2(r2, xb.u[0], acc2[kk * 4 + 2]);
                acc2[kk * 4 + 3] = fma2(r2, xb.u[1], acc2[kk * 4 + 3]);
            }
        }
    }

    // red-atomic partial P into out[b]
    float* ob = out + b * (KK * DD);
    #pragma unroll
    for (int kk = 0; kk < 8; kk++) {
        int kr = (w * 8 + kk) * DD;
        #pragma unroll
        for (int p = 0; p < 2; p++) {
            float2 v = unpack2(acc2[kk * 4 + p]);
            atomicAdd(ob + kr + 4 * lane + 2 * p,     v.x);
            atomicAdd(ob + kr + 4 * lane + 2 * p + 1, v.y);
        }
        #pragma unroll
        for (int p = 0; p < 2; p++) {
            float2 v = unpack2(acc2[kk * 4 + 2 + p]);
            atomicAdd(ob + kr + 128 + 4 * lane + 2 * p,     v.x);
            atomicAdd(ob + kr + 128 + 4 * lane + 2 * p + 1, v.y);
        }
    }
}

__global__ __launch_bounds__(256, 1)
void fused_kernel(const float* __restrict__ x, const float* __restrict__ mu,
                  float* __restrict__ out) {
    int bx = blockIdx.x;
    if (bx < 128) {
        int b = bx >> 3;
        fused_body<96>(b, b * TT + (bx & 7) * 96, x, mu, out);
    } else {
        int b = bx - 128;
        fused_body<32>(b, b * TT + 768, x, mu, out);
    }
}

// smem: NR=96 -> (96*66 + 64*66)*4 + 96*64*8 + 96*4 = 42240 + 49152 + 384 = 91776
#define FUSED_SMEM 92160

// ---------------- finalize: out = (P - mu*S)/(S+1e-9), 2 f4 per thread --------
__global__ void finalize_kernel(const float* __restrict__ mu, float* __restrict__ out) {
    int base = blockIdx.x * 256 + threadIdx.x;
    #pragma unroll
    for (int h = 0; h < 2; h++) {
        int i = base + h * 32768;              // float4 index, 65536 total
        int bb = i >> 12;
        int k  = (i >> 6) & 63;
        float s = g_S[bb * 64 + k];
        float inv = 1.f / (s + 1e-9f);
        float4 p = ((const float4*)out)[i];
        float4 m = ((const float4*)mu)[i & 4095];
        float4 o;
        o.x = (p.x - m.x * s) * inv;
        o.y = (p.y - m.y * s) * inv;
        o.z = (p.z - m.z * s) * inv;
        o.w = (p.w - m.w * s) * inv;
        ((float4*)out)[i] = o;
    }
}

// ---------------- launcher ------------------------------------------------------
extern "C" void kernel_launch(void* const* d_in, const int* in_sizes, int n_in,
                              void* d_out, int out_size) {
    const float* x    = (const float*)d_in[0];
    const float* mu   = (const float*)d_in[1];
    const float* prec = (const float*)d_in[2];
    float* out = (float*)d_out;

    static int smem_set = 0;
    if (!smem_set) {
        cudaFuncSetAttribute(fused_kernel, cudaFuncAttributeMaxDynamicSharedMemorySize,
                             FUSED_SMEM);
        smem_set = 1;
    }

    prep_kernel<<<257, 256>>>(mu, prec, out);
    fused_kernel<<<144, 256, FUSED_SMEM>>>(x, mu, out);
    finalize_kernel<<<128, 256>>>(mu, out);
}

// round 4
// speedup vs baseline: 2.3155x; 1.5222x over previous
#include <cuda_runtime.h>

// Problem constants: x (16,800,256), mu (64,256), prec (64) -> out (16, 64*256)
#define BB 16
#define TT 800
#define DD 256
#define KK 64
#define NSLOT 9   // 8 blocks of 96 rows + 1 block of 32 rows per batch

typedef unsigned long long ull;

// ---------------- scratch (device globals; fully overwritten every call) -------
__device__ float g_P[BB * NSLOT * KK * DD];   // per-slot pool partials, 9.4MB
__device__ float g_Ssl[BB * NSLOT * KK];      // per-slot softmax sums

// ---------------- f32x2 helpers -------------------------------------------------
__device__ __forceinline__ ull pack2(float lo, float hi) {
    ull r; asm("mov.b64 %0,{%1,%2};" : "=l"(r) : "f"(lo), "f"(hi)); return r;
}
__device__ __forceinline__ ull fma2(ull a, ull b, ull c) {
    ull d; asm("fma.rn.f32x2 %0,%1,%2,%3;" : "=l"(d) : "l"(a), "l"(b), "l"(c)); return d;
}
__device__ __forceinline__ float2 unpack2(ull v) {
    float2 f; asm("mov.b64 {%0,%1},%2;" : "=f"(f.x), "=f"(f.y) : "l"(v)); return f;
}

union F4 { float4 f; ull u[2]; };

// ---------------- fused body: llk GEMM + softmax + pool GEMM --------------------
template<int NR>
__device__ __forceinline__ void fused_body(int b, int slot, int trow0,
                                           const float* __restrict__ x,
                                           const float* __restrict__ mu,
                                           const float* __restrict__ prec) {
    constexpr int RT  = NR / 16;   // rows per thread (phase A)
    constexpr int RPW = NR / 8;    // rows per warp (phase B)

    extern __shared__ char sm[];
    float* sx    = (float*)sm;             // NR*66
    float* smu   = sx + NR * 66;           // 64*66
    float* sr    = smu + 64 * 66;          // NR*64
    float* sxsq  = sr + NR * 64;           // NR
    float* smusq = sxsq + NR;              // 64
    float* sS    = smusq + 64;             // 8*64 per-warp softmax-sum partials
    float*  sG = sx;                       // phase B overlay (NR*64 <= NR*66)
    float4* xs = (float4*)sx;              // phase C overlay (16*64 f4 = 16KB)

    int tid  = threadIdx.x;
    int lane = tid & 31;
    int w    = tid >> 5;
    int kg   = tid >> 4;   // k group: k in [4kg, 4kg+4)
    int rg   = tid & 15;   // rows {rg, rg+16, ...}

    const float4* x4  = (const float4*)x;
    const float4* mu4 = (const float4*)mu;

    ull acc[RT * 4];
    #pragma unroll
    for (int i = 0; i < RT * 4; i++) acc[i] = 0ull;
    float myxsq[RT];
    #pragma unroll
    for (int i = 0; i < RT; i++) myxsq[i] = 0.f;
    float mymusq[4] = {0.f, 0.f, 0.f, 0.f};

    // prefetch chunk 0
    float4 px[RT], pm[4];
    #pragma unroll
    for (int ii = 0; ii < RT; ii++) {
        int idx = tid + 256 * ii;
        px[ii] = x4[(trow0 + (idx >> 4)) * 64 + (idx & 15)];
    }
    #pragma unroll
    for (int ii = 0; ii < 4; ii++) {
        int idx = tid + 256 * ii;
        pm[ii] = mu4[(idx >> 4) * 64 + (idx & 15)];
    }

    // ---- Phase A: distance GEMM over 4 chunks of 64 d ----
    for (int c = 0; c < 4; c++) {
        __syncthreads();
        #pragma unroll
        for (int ii = 0; ii < RT; ii++) {
            int idx = tid + 256 * ii;
            int r = idx >> 4, j = idx & 15;
            float4 v = px[ii];
            myxsq[ii] += v.x * v.x + v.y * v.y + v.z * v.z + v.w * v.w;
            float2* d = (float2*)(sx + r * 66 + j * 4);
            d[0] = make_float2(v.x, v.y); d[1] = make_float2(v.z, v.w);
        }
        #pragma unroll
        for (int ii = 0; ii < 4; ii++) {
            int idx = tid + 256 * ii;
            int r = idx >> 4, j = idx & 15;
            float4 m = pm[ii];
            mymusq[ii] += m.x * m.x + m.y * m.y + m.z * m.z + m.w * m.w;
            float2* dm = (float2*)(smu + r * 66 + j * 4);
            dm[0] = make_float2(m.x, m.y); dm[1] = make_float2(m.z, m.w);
        }
        __syncthreads();
        if (c < 3) {   // prefetch next chunk while computing this one
            #pragma unroll
            for (int ii = 0; ii < RT; ii++) {
                int idx = tid + 256 * ii;
                px[ii] = x4[(trow0 + (idx >> 4)) * 64 + (c + 1) * 16 + (idx & 15)];
            }
            #pragma unroll
            for (int ii = 0; ii < 4; ii++) {
                int idx = tid + 256 * ii;
                pm[ii] = mu4[(idx >> 4) * 64 + (c + 1) * 16 + (idx & 15)];
            }
        }
        #pragma unroll 4
        for (int dp = 0; dp < 32; dp++) {
            ull xv[RT], mv[4];
            #pragma unroll
            for (int i = 0; i < RT; i++)
                xv[i] = *(const ull*)(sx + (rg + 16 * i) * 66 + 2 * dp);
            #pragma unroll
            for (int j = 0; j < 4; j++)
                mv[j] = *(const ull*)(smu + (kg * 4 + j) * 66 + 2 * dp);
            #pragma unroll
            for (int i = 0; i < RT; i++)
                #pragma unroll
                for (int j = 0; j < 4; j++)
                    acc[i * 4 + j] = fma2(xv[i], mv[j], acc[i * 4 + j]);
        }
    }

    // reduce xsq / musq across the 16 threads sharing a row (shuffle, no atomics)
    #pragma unroll
    for (int o = 1; o < 16; o <<= 1) {
        #pragma unroll
        for (int ii = 0; ii < RT; ii++)
            myxsq[ii] += __shfl_xor_sync(0xffffffffu, myxsq[ii], o);
        #pragma unroll
        for (int ii = 0; ii < 4; ii++)
            mymusq[ii] += __shfl_xor_sync(0xffffffffu, mymusq[ii], o);
    }
    if ((tid & 15) == 0) {
        #pragma unroll
        for (int ii = 0; ii < RT; ii++) sxsq[(tid >> 4) + 16 * ii] = myxsq[ii];
        #pragma unroll
        for (int ii = 0; ii < 4; ii++)  smusq[(tid >> 4) + 16 * ii] = mymusq[ii];
    }
    __syncthreads();

    // dump G tile (overlay on sx)
    #pragma unroll
    for (int i = 0; i < RT; i++) {
        int row = rg + 16 * i;
        #pragma unroll
        for (int j = 0; j < 4; j++) {
            float2 v = unpack2(acc[i * 4 + j]);
            sG[row * 64 + kg * 4 + j] = v.x + v.y;
        }
    }
    __syncthreads();

    // ---- Phase B: softmax over K, r -> sr, per-warp S partials -> sS ----
    {
        float p0 = prec[lane], p1 = prec[lane + 32];
        float pp0 = p0 * p0, pp1 = p1 * p1;
        float mq0 = smusq[lane], mq1 = smusq[lane + 32];
        float ss0 = 0.f, ss1 = 0.f;
        #pragma unroll
        for (int rr = 0; rr < RPW; rr++) {
            int row = w * RPW + rr;
            float xq = sxsq[row];
            float G0 = sG[row * 64 + lane];
            float G1 = sG[row * 64 + lane + 32];
            float l0 = -pp0 * (xq - 2.f * G0 + mq0);
            float l1 = -pp1 * (xq - 2.f * G1 + mq1);
            float m = fmaxf(l0, l1);
            #pragma unroll
            for (int o = 16; o; o >>= 1) m = fmaxf(m, __shfl_xor_sync(0xffffffffu, m, o));
            float e0 = __expf(l0 - m), e1 = __expf(l1 - m);
            float s = e0 + e1;
            #pragma unroll
            for (int o = 16; o; o >>= 1) s += __shfl_xor_sync(0xffffffffu, s, o);
            float inv = 1.f / s;
            float r0 = e0 * inv, r1 = e1 * inv;
            sr[row * 64 + lane]      = r0;
            sr[row * 64 + lane + 32] = r1;
            ss0 += r0; ss1 += r1;
        }
        sS[w * 64 + lane]      = ss0;   // per-warp partial (fixes round-3 race)
        sS[w * 64 + lane + 32] = ss1;
    }
    __syncthreads();
    if (tid < 64) {      // cross-warp reduce, single deterministic slot write
        float S = 0.f;
        #pragma unroll
        for (int ww = 0; ww < 8; ww++) S += sS[ww * 64 + tid];
        g_Ssl[(b * NSLOT + slot) * 64 + tid] = S;
    }

    // ---- Phase C: pool GEMM, thread tile 8k x 8d, reg-prefetch pipeline ----
    ull acc2[32];
    #pragma unroll
    for (int i = 0; i < 32; i++) acc2[i] = 0ull;

    float4 pc[4];
    #pragma unroll
    for (int ii = 0; ii < 4; ii++) {
        int idx = tid + 256 * ii;
        pc[ii] = x4[(trow0 + (idx >> 6)) * 64 + (idx & 63)];
    }

    for (int st = 0; st < NR / 16; st++) {
        __syncthreads();
        #pragma unroll
        for (int ii = 0; ii < 4; ii++) xs[tid + 256 * ii] = pc[ii];
        __syncthreads();
        if (st < NR / 16 - 1) {
            #pragma unroll
            for (int ii = 0; ii < 4; ii++) {
                int idx = tid + 256 * ii;
                pc[ii] = x4[(trow0 + (st + 1) * 16 + (idx >> 6)) * 64 + (idx & 63)];
            }
        }
        #pragma unroll
        for (int tt = 0; tt < 16; tt++) {
            const float* rk = &sr[(st * 16 + tt) * 64 + w * 8];
            F4 xa, xb;
            xa.f = xs[tt * 64 + lane];
            xb.f = xs[tt * 64 + 32 + lane];
            #pragma unroll
            for (int kk = 0; kk < 8; kk++) {
                float rv = rk[kk];                 // warp-uniform -> broadcast LDS
                ull r2 = pack2(rv, rv);
                acc2[kk * 4 + 0] = fma2(r2, xa.u[0], acc2[kk * 4 + 0]);
                acc2[kk * 4 + 1] = fma2(r2, xa.u[1], acc2[kk * 4 + 1]);
                acc2[kk * 4 + 2] = fma2(r2, xb.u[0], acc2[kk * 4 + 2]);
                acc2[kk * 4 + 3] = fma2(r2, xb.u[1], acc2[kk * 4 + 3]);
            }
        }
    }

    // plain STG of the partial tile into this block's private slot (no atomics)
    float4* pslot = (float4*)(g_P + (b * NSLOT + slot) * (KK * DD));
    #pragma unroll
    for (int kk = 0; kk < 8; kk++) {
        int kr = (w * 8 + kk) * 64;    // float4 row pitch = 64
        F4 v0, v1;
        v0.u[0] = acc2[kk * 4 + 0]; v0.u[1] = acc2[kk * 4 + 1];
        v1.u[0] = acc2[kk * 4 + 2]; v1.u[1] = acc2[kk * 4 + 3];
        pslot[kr + lane]      = v0.f;   // d = 4*lane
        pslot[kr + 32 + lane] = v1.f;   // d = 128 + 4*lane
    }
}

__global__ __launch_bounds__(256, 1)
void fused_kernel(const float* __restrict__ x, const float* __restrict__ mu,
                  const float* __restrict__ prec) {
    int bx = blockIdx.x;
    if (bx < 128) {
        int b = bx >> 3, slot = bx & 7;
        fused_body<96>(b, slot, b * TT + slot * 96, x, mu, prec);
    } else {
        int b = bx - 128;
        fused_body<32>(b, 8, b * TT + 768, x, mu, prec);
    }
}

// smem: (96*66 + 64*66 + 96*64 + 96 + 64 + 512) * 4 = 69504 bytes
#define FUSED_SMEM 69504

// ---------------- finalize: out = (sum_slots P - mu*S)/(S+1e-9) -----------------
__global__ __launch_bounds__(256, 8)
void finalize_kernel(const float* __restrict__ mu, float* __restrict__ out) {
    int bx = blockIdx.x;
    int b = bx >> 3;
    int k = (bx & 7) * 8 + (threadIdx.x >> 5);
    int lane = threadIdx.x & 31;

    float S = 0.f;
    const float* ss = g_Ssl + b * NSLOT * 64 + k;
    #pragma unroll
    for (int s = 0; s < NSLOT; s++) S += ss[s * 64];
    float inv = 1.f / (S + 1e-9f);

    const float4* pb  = (const float4*)g_P + (b * NSLOT * 64 + k) * 64;
    const float4* mu4 = (const float4*)mu + k * 64;
    float4* ob = (float4*)out + (b * 64 + k) * 64;

    #pragma unroll
    for (int h = 0; h < 2; h++) {
        int d4 = lane + 32 * h;
        float4 a = make_float4(0.f, 0.f, 0.f, 0.f);
        #pragma unroll
        for (int s = 0; s < NSLOT; s++) {
            float4 v = pb[s * 64 * 64 + d4];
            a.x += v.x; a.y += v.y; a.z += v.z; a.w += v.w;
        }
        float4 m = mu4[d4];
        float4 o;
        o.x = (a.x - m.x * S) * inv;
        o.y = (a.y - m.y * S) * inv;
        o.z = (a.z - m.z * S) * inv;
        o.w = (a.w - m.w * S) * inv;
        ob[d4] = o;
    }
}

// ---------------- launcher --------------------------------------------------------
extern "C" void kernel_launch(void* const* d_in, const int* in_sizes, int n_in,
                              void* d_out, int out_size) {
    const float* x    = (const float*)d_in[0];
    const float* mu   = (const float*)d_in[1];
    const float* prec = (const float*)d_in[2];
    float* out = (float*)d_out;

    cudaFuncSetAttribute(fused_kernel, cudaFuncAttributeMaxDynamicSharedMemorySize,
                         FUSED_SMEM);

    fused_kernel<<<144, 256, FUSED_SMEM>>>(x, mu, prec);
    finalize_kernel<<<128, 256>>>(mu, out);
}

// round 5
// speedup vs baseline: 2.4417x; 1.0545x over previous
#include <cuda_runtime.h>

// Problem constants: x (16,800,256), mu (64,256), prec (64) -> out (16, 64*256)
#define BB 16
#define TT 800
#define DD 256
#define KK 64
#define NSLOT 9   // 8 blocks of 96 rows + 1 block of 32 rows per batch
#define PX 68     // smem pitch for sx/smu (16B-aligned rows, conflict-free)
#define PG 65     // smem pitch for sG (kills STS bank conflicts in dump)

typedef unsigned long long ull;

// ---------------- scratch (device globals; fully overwritten every call) -------
__device__ float g_P[BB * NSLOT * KK * DD];   // per-slot pool partials, 9.4MB
__device__ float g_Ssl[BB * NSLOT * KK];      // per-slot softmax sums

// ---------------- f32x2 helpers -------------------------------------------------
__device__ __forceinline__ ull pack2(float lo, float hi) {
    ull r; asm("mov.b64 %0,{%1,%2};" : "=l"(r) : "f"(lo), "f"(hi)); return r;
}
__device__ __forceinline__ ull fma2(ull a, ull b, ull c) {
    ull d; asm("fma.rn.f32x2 %0,%1,%2,%3;" : "=l"(d) : "l"(a), "l"(b), "l"(c)); return d;
}
__device__ __forceinline__ float2 unpack2(ull v) {
    float2 f; asm("mov.b64 {%0,%1},%2;" : "=f"(f.x), "=f"(f.y) : "l"(v)); return f;
}

union F4 { float4 f; ull u[2]; };

// ---------------- fused body: llk GEMM + softmax + pool GEMM --------------------
// Phase A: G = X*MU^T. Warp w owns k in [8w,8w+8) (broadcast mu loads);
//          lane owns rows {lane, lane+32, lane+64}. Tile 3r x 8k, LDS.128 x.
// Phase B: softmax over K -> r in smem, per-slot S (warp partials + reduce).
// Phase C: P_slot = r^T * X, 8k x 8d thread tiles, plain STG to g_P.
template<int NR>
__device__ __forceinline__ void fused_body(int b, int slot, int trow0,
                                           const float* __restrict__ x,
                                           const float* __restrict__ mu,
                                           const float* __restrict__ prec) {
    constexpr int RT  = NR / 16;   // staging loads per thread
    constexpr int RPW = NR / 8;    // rows per warp (phase B)
    constexpr int RL  = NR / 32;   // rows per lane (phase A compute)

    extern __shared__ char sm[];
    float* sx    = (float*)sm;             // NR*PX
    float* smu   = sx + NR * PX;           // 64*PX
    float* sr    = smu + 64 * PX;          // NR*64
    float* sxsq  = sr + NR * 64;           // NR
    float* smusq = sxsq + NR;              // 64
    float* sS    = smusq + 64;             // 8*64 per-warp softmax-sum partials
    float*  sG = sx;                       // phase B overlay: NR*PG <= NR*PX
    float4* xs = (float4*)sx;              // phase C overlay: 16*64 f4 = 16KB

    int tid  = threadIdx.x;
    int lane = tid & 31;
    int w    = tid >> 5;

    const float4* x4  = (const float4*)x;
    const float4* mu4 = (const float4*)mu;

    ull acc[RL * 8];
    #pragma unroll
    for (int i = 0; i < RL * 8; i++) acc[i] = 0ull;
    float myxsq[RT];
    #pragma unroll
    for (int i = 0; i < RT; i++) myxsq[i] = 0.f;
    float mymusq[4] = {0.f, 0.f, 0.f, 0.f};

    // prefetch chunk 0 (staging layout: 16 threads per row, j = tid&15)
    float4 px[RT], pm[4];
    #pragma unroll
    for (int ii = 0; ii < RT; ii++) {
        int idx = tid + 256 * ii;
        px[ii] = x4[(trow0 + (idx >> 4)) * 64 + (idx & 15)];
    }
    #pragma unroll
    for (int ii = 0; ii < 4; ii++) {
        int idx = tid + 256 * ii;
        pm[ii] = mu4[(idx >> 4) * 64 + (idx & 15)];
    }

    // ---- Phase A: distance GEMM over 4 chunks of 64 d ----
    for (int c = 0; c < 4; c++) {
        __syncthreads();
        #pragma unroll
        for (int ii = 0; ii < RT; ii++) {
            int idx = tid + 256 * ii;
            int r = idx >> 4, j = idx & 15;
            float4 v = px[ii];
            myxsq[ii] += v.x * v.x + v.y * v.y + v.z * v.z + v.w * v.w;
            *(float4*)(sx + r * PX + 4 * j) = v;
        }
        #pragma unroll
        for (int ii = 0; ii < 4; ii++) {
            int idx = tid + 256 * ii;
            int r = idx >> 4, j = idx & 15;
            float4 m = pm[ii];
            mymusq[ii] += m.x * m.x + m.y * m.y + m.z * m.z + m.w * m.w;
            *(float4*)(smu + r * PX + 4 * j) = m;
        }
        __syncthreads();
        if (c < 3) {   // prefetch next chunk while computing this one
            #pragma unroll
            for (int ii = 0; ii < RT; ii++) {
                int idx = tid + 256 * ii;
                px[ii] = x4[(trow0 + (idx >> 4)) * 64 + (c + 1) * 16 + (idx & 15)];
            }
            #pragma unroll
            for (int ii = 0; ii < 4; ii++) {
                int idx = tid + 256 * ii;
                pm[ii] = mu4[(idx >> 4) * 64 + (c + 1) * 16 + (idx & 15)];
            }
        }
        // compute: 16 iterations of 4 d (2 d-pairs) each
        #pragma unroll 2
        for (int q = 0; q < 16; q++) {
            F4 mv[8], xv[RL];
            #pragma unroll
            for (int j = 0; j < 8; j++)
                mv[j].f = *(const float4*)(smu + (w * 8 + j) * PX + 4 * q);  // broadcast
            #pragma unroll
            for (int i = 0; i < RL; i++)
                xv[i].f = *(const float4*)(sx + (lane + 32 * i) * PX + 4 * q);
            #pragma unroll
            for (int i = 0; i < RL; i++)
                #pragma unroll
                for (int j = 0; j < 8; j++) {
                    acc[i * 8 + j] = fma2(xv[i].u[0], mv[j].u[0], acc[i * 8 + j]);
                    acc[i * 8 + j] = fma2(xv[i].u[1], mv[j].u[1], acc[i * 8 + j]);
                }
        }
    }

    // reduce xsq / musq across the 16 threads sharing a staging row
    #pragma unroll
    for (int o = 1; o < 16; o <<= 1) {
        #pragma unroll
        for (int ii = 0; ii < RT; ii++)
            myxsq[ii] += __shfl_xor_sync(0xffffffffu, myxsq[ii], o);
        #pragma unroll
        for (int ii = 0; ii < 4; ii++)
            mymusq[ii] += __shfl_xor_sync(0xffffffffu, mymusq[ii], o);
    }
    __syncthreads();   // everyone done reading sx before sG overlay
    if ((tid & 15) == 0) {
        #pragma unroll
        for (int ii = 0; ii < RT; ii++) sxsq[(tid >> 4) + 16 * ii] = myxsq[ii];
        #pragma unroll
        for (int ii = 0; ii < 4; ii++)  smusq[(tid >> 4) + 16 * ii] = mymusq[ii];
    }

    // dump G tile (overlay on sx, pitch PG)
    #pragma unroll
    for (int i = 0; i < RL; i++) {
        int row = lane + 32 * i;
        #pragma unroll
        for (int j = 0; j < 8; j++) {
            float2 v = unpack2(acc[i * 8 + j]);
            sG[row * PG + w * 8 + j] = v.x + v.y;
        }
    }
    __syncthreads();

    // ---- Phase B: softmax over K, r -> sr, per-warp S partials -> sS ----
    {
        float p0 = prec[lane], p1 = prec[lane + 32];
        float pp0 = p0 * p0, pp1 = p1 * p1;
        float mq0 = smusq[lane], mq1 = smusq[lane + 32];
        float ss0 = 0.f, ss1 = 0.f;
        #pragma unroll
        for (int rr = 0; rr < RPW; rr++) {
            int row = w * RPW + rr;
            float xq = sxsq[row];
            float G0 = sG[row * PG + lane];
            float G1 = sG[row * PG + lane + 32];
            float l0 = -pp0 * (xq - 2.f * G0 + mq0);
            float l1 = -pp1 * (xq - 2.f * G1 + mq1);
            float m = fmaxf(l0, l1);
            #pragma unroll
            for (int o = 16; o; o >>= 1) m = fmaxf(m, __shfl_xor_sync(0xffffffffu, m, o));
            float e0 = __expf(l0 - m), e1 = __expf(l1 - m);
            float s = e0 + e1;
            #pragma unroll
            for (int o = 16; o; o >>= 1) s += __shfl_xor_sync(0xffffffffu, s, o);
            float inv = 1.f / s;
            float r0 = e0 * inv, r1 = e1 * inv;
            sr[row * 64 + lane]      = r0;
            sr[row * 64 + lane + 32] = r1;
            ss0 += r0; ss1 += r1;
        }
        sS[w * 64 + lane]      = ss0;
        sS[w * 64 + lane + 32] = ss1;
    }
    __syncthreads();
    if (tid < 64) {      // cross-warp reduce, single deterministic slot write
        float S = 0.f;
        #pragma unroll
        for (int ww = 0; ww < 8; ww++) S += sS[ww * 64 + tid];
        g_Ssl[(b * NSLOT + slot) * 64 + tid] = S;
    }

    // ---- Phase C: pool GEMM, thread tile 8k x 8d, reg-prefetch pipeline ----
    ull acc2[32];
    #pragma unroll
    for (int i = 0; i < 32; i++) acc2[i] = 0ull;

    float4 pc[4];
    #pragma unroll
    for (int ii = 0; ii < 4; ii++) {
        int idx = tid + 256 * ii;
        pc[ii] = x4[(trow0 + (idx >> 6)) * 64 + (idx & 63)];
    }

    for (int st = 0; st < NR / 16; st++) {
        __syncthreads();
        #pragma unroll
        for (int ii = 0; ii < 4; ii++) xs[tid + 256 * ii] = pc[ii];
        __syncthreads();
        if (st < NR / 16 - 1) {
            #pragma unroll
            for (int ii = 0; ii < 4; ii++) {
                int idx = tid + 256 * ii;
                pc[ii] = x4[(trow0 + (st + 1) * 16 + (idx >> 6)) * 64 + (idx & 63)];
            }
        }
        #pragma unroll
        for (int tt = 0; tt < 16; tt++) {
            const float* rk = &sr[(st * 16 + tt) * 64 + w * 8];
            ull rp[4];
            #pragma unroll
            for (int m = 0; m < 4; m++)
                rp[m] = *(const ull*)(rk + 2 * m);    // broadcast LDS.64
            F4 xa, xb;
            xa.f = xs[tt * 64 + lane];
            xb.f = xs[tt * 64 + 32 + lane];
            #pragma unroll
            for (int m = 0; m < 4; m++) {
                float2 rr = unpack2(rp[m]);
                ull r2a = pack2(rr.x, rr.x);
                ull r2b = pack2(rr.y, rr.y);
                int ka = (2 * m) * 4, kb = (2 * m + 1) * 4;
                acc2[ka + 0] = fma2(r2a, xa.u[0], acc2[ka + 0]);
                acc2[ka + 1] = fma2(r2a, xa.u[1], acc2[ka + 1]);
                acc2[ka + 2] = fma2(r2a, xb.u[0], acc2[ka + 2]);
                acc2[ka + 3] = fma2(r2a, xb.u[1], acc2[ka + 3]);
                acc2[kb + 0] = fma2(r2b, xa.u[0], acc2[kb + 0]);
                acc2[kb + 1] = fma2(r2b, xa.u[1], acc2[kb + 1]);
                acc2[kb + 2] = fma2(r2b, xb.u[0], acc2[kb + 2]);
                acc2[kb + 3] = fma2(r2b, xb.u[1], acc2[kb + 3]);
            }
        }
    }

    // plain STG of the partial tile into this block's private slot (no atomics)
    float4* pslot = (float4*)(g_P + (b * NSLOT + slot) * (KK * DD));
    #pragma unroll
    for (int kk = 0; kk < 8; kk++) {
        int kr = (w * 8 + kk) * 64;    // float4 row pitch = 64
        F4 v0, v1;
        v0.u[0] = acc2[kk * 4 + 0]; v0.u[1] = acc2[kk * 4 + 1];
        v1.u[0] = acc2[kk * 4 + 2]; v1.u[1] = acc2[kk * 4 + 3];
        pslot[kr + lane]      = v0.f;   // d = 4*lane
        pslot[kr + 32 + lane] = v1.f;   // d = 128 + 4*lane
    }
}

__global__ __launch_bounds__(256, 1)
void fused_kernel(const float* __restrict__ x, const float* __restrict__ mu,
                  const float* __restrict__ prec) {
    int bx = blockIdx.x;
    if (bx < 128) {
        int b = bx >> 3, slot = bx & 7;
        fused_body<96>(b, slot, b * TT + slot * 96, x, mu, prec);
    } else {
        int b = bx - 128;
        fused_body<32>(b, 8, b * TT + 768, x, mu, prec);
    }
}

// smem: (96*68 + 64*68 + 96*64 + 96 + 64 + 512) * 4 = 70784 bytes
#define FUSED_SMEM 70784

// ---------------- finalize: out = (sum_slots P - mu*S)/(S+1e-9) -----------------
// 65536 threads, one float4 each, 9 independent slot loads (full MLP).
__global__ __launch_bounds__(256, 8)
void finalize_kernel(const float* __restrict__ mu, float* __restrict__ out) {
    int i = blockIdx.x * 256 + threadIdx.x;   // float4 index in [0, 65536)
    int b  = i >> 12;
    int k  = (i >> 6) & 63;
    int d4 = i & 63;

    const float* ss = g_Ssl + b * NSLOT * 64 + k;
    float S = 0.f;
    #pragma unroll
    for (int s = 0; s < NSLOT; s++) S += ss[s * 64];
    float inv = 1.f / (S + 1e-9f);

    const float4* pb = (const float4*)g_P + b * NSLOT * 4096 + k * 64 + d4;
    float4 a = make_float4(0.f, 0.f, 0.f, 0.f);
    #pragma unroll
    for (int s = 0; s < NSLOT; s++) {
        float4 v = pb[s * 4096];
        a.x += v.x; a.y += v.y; a.z += v.z; a.w += v.w;
    }
    float4 m = ((const float4*)mu)[k * 64 + d4];
    float4 o;
    o.x = (a.x - m.x * S) * inv;
    o.y = (a.y - m.y * S) * inv;
    o.z = (a.z - m.z * S) * inv;
    o.w = (a.w - m.w * S) * inv;
    ((float4*)out)[i] = o;
}

// ---------------- launcher --------------------------------------------------------
extern "C" void kernel_launch(void* const* d_in, const int* in_sizes, int n_in,
                              void* d_out, int out_size) {
    const float* x    = (const float*)d_in[0];
    const float* mu   = (const float*)d_in[1];
    const float* prec = (const float*)d_in[2];
    float* out = (float*)d_out;

    cudaFuncSetAttribute(fused_kernel, cudaFuncAttributeMaxDynamicSharedMemorySize,
                         FUSED_SMEM);

    fused_kernel<<<144, 256, FUSED_SMEM>>>(x, mu, prec);
    finalize_kernel<<<256, 256>>>(mu, out);
}